// round 1
// baseline (speedup 1.0000x reference)
#include <cuda_runtime.h>

#define SPB 8            // samples per block
#define TPS 64           // threads per sample
#define THREADS (SPB*TPS)
#define STRIDE 68        // padded row stride for 8x64 buffers (bank-conflict free, 16B-aligned)

// ---- weight offsets in shared (floats) ----
enum {
  EW1=0,      EB1=192,   EW2=256,   EB2=4352,  EW3=4416,  EB3=4608,
  G1WL=4612,  G1BL=4804, G1WR=4868, G1BR=5060, G1WE=5124, G1ATT=5188, G1BIAS=5252,
  G2WL=5316,  G2BL=5508, G2WR=5512, G2BR=5704, G2WE=5708, G2ATT=5712, G2BIAS=5716,
  SKW=5720,   SKB=5732,
  DW1=5736,   DB1=5928,  DW2=5992,  DB2=10088, DW3=10152, DB3=10344,
  WTOT=10348
};
// ---- per-sample scratch offsets (floats) ----
enum {
  S_A=0, S_B=544, S_LAT=1088, S_VIS=1120, S_EAT=1152, S_MASK=1224, S_ALPHA=1296,
  S_XL2=1368, S_XR2=1400, S_COMB=1432, S_H2O=1464, S_X=1496, S_RED=1504, S_PER=1520
};

#define SMEM_FLOATS (WTOT + SPB*S_PER)
#define SMEM_BYTES  (SMEM_FLOATS*4)

struct KParams {
  const float* x;
  const float* w[28];
  int B;
};

extern __shared__ float smem[];

// 8x64 @ 64x64 layer with relu: thread t -> (node n = t>>3, channel group cg = t&7)
__device__ __forceinline__ void mlp64x64(const float* __restrict__ in, float* __restrict__ outp,
                                         const float* __restrict__ W, const float* __restrict__ b, int t)
{
  int n = t >> 3, cg = t & 7;
  float acc[8];
#pragma unroll
  for (int u = 0; u < 8; u++) acc[u] = b[cg*8 + u];
#pragma unroll 16
  for (int k = 0; k < 64; k++) {
    float a = in[n*STRIDE + k];
    const float4* wp = reinterpret_cast<const float4*>(W + k*64 + cg*8);
    float4 w0 = wp[0], w1 = wp[1];
    acc[0] = fmaf(a, w0.x, acc[0]); acc[1] = fmaf(a, w0.y, acc[1]);
    acc[2] = fmaf(a, w0.z, acc[2]); acc[3] = fmaf(a, w0.w, acc[3]);
    acc[4] = fmaf(a, w1.x, acc[4]); acc[5] = fmaf(a, w1.y, acc[5]);
    acc[6] = fmaf(a, w1.z, acc[6]); acc[7] = fmaf(a, w1.w, acc[7]);
  }
#pragma unroll
  for (int u = 0; u < 8; u++) outp[n*STRIDE + cg*8 + u] = fmaxf(acc[u], 0.f);
}

__global__ __launch_bounds__(THREADS, 2)
void gae_kernel(KParams kp, float* __restrict__ out)
{
  float* ws = smem;
  const int tid = threadIdx.x;

  // ---- stage all weights into shared ----
  {
    const int cnts[28] = {192,64,4096,64,192,3, 192,64,192,64,64,64,64,
                          192,3,192,3,3,3,3, 9,3, 192,64,4096,64,192,3};
    const int offs[28] = {EW1,EB1,EW2,EB2,EW3,EB3, G1WL,G1BL,G1WR,G1BR,G1WE,G1ATT,G1BIAS,
                          G2WL,G2BL,G2WR,G2BR,G2WE,G2ATT,G2BIAS, SKW,SKB,
                          DW1,DB1,DW2,DB2,DW3,DB3};
#pragma unroll
    for (int a = 0; a < 28; a++) {
      const float* src = kp.w[a];
      for (int i = tid; i < cnts[a]; i += THREADS) ws[offs[a] + i] = src[i];
    }
  }

  const int g = tid / TPS;
  const int t = tid % TPS;
  float* sc = smem + WTOT + g*S_PER;
  const int Btot = kp.B;
  const int s = blockIdx.x*SPB + g;
  const bool valid = (s < Btot);
  const int sl = valid ? s : 0;

  if (t < 8) sc[S_X + t] = kp.x[sl*8 + t];
  __syncthreads();

  // ================= encoder =================
  // L1: [0, n, x] @ w1 + b1, relu  (thread = output channel)
  {
    float w1n = ws[EW1 + 64 + t], w1x = ws[EW1 + 128 + t], b = ws[EB1 + t];
#pragma unroll
    for (int n = 0; n < 8; n++) {
      float h = fmaf((float)n, w1n, fmaf(sc[S_X + n], w1x, b));
      sc[S_A + n*STRIDE + t] = fmaxf(h, 0.f);
    }
  }
  __syncthreads();
  // L2
  mlp64x64(sc + S_A, sc + S_B, ws + EW2, ws + EB2, t);
  __syncthreads();
  // L3 -> latent [8][3]
  if (t < 24) {
    int n = t / 3, l = t % 3;
    float acc = ws[EB3 + l];
#pragma unroll 16
    for (int k = 0; k < 64; k++) acc = fmaf(sc[S_B + n*STRIDE + k], ws[EW3 + k*3 + l], acc);
    sc[S_LAT + n*4 + l] = acc;
  }
  __syncthreads();

  // ================= normalize -> vis =================
  if (t < 3) {
    float m = 0.f;
#pragma unroll
    for (int n = 0; n < 8; n++) m += sc[S_LAT + n*4 + t];
    m *= 0.125f;
    float v = 0.f, c[8];
#pragma unroll
    for (int n = 0; n < 8; n++) { c[n] = sc[S_LAT + n*4 + t] - m; v += c[n]*c[n]; }
    float inv = 1.f / (sqrtf(v * (1.f/7.f)) + 1e-8f);
#pragma unroll
    for (int n = 0; n < 8; n++) sc[S_VIS + n*4 + t] = c[n]*inv;
  }
  __syncthreads();

  // outputs: xp (offset 0) and vis (offset 2*B*24)
  if (valid && t < 24) {
    int n = t / 3, f = t % 3;
    float xpv = (f == 0) ? 0.f : (f == 1 ? (float)n : sc[S_X + n]);
    out[s*24 + t] = xpv;
    out[2*Btot*24 + s*24 + t] = sc[S_VIS + n*4 + f];
  }

  // ================= Gabriel graph =================
  {
    int i = t >> 3, j = t & 7;
    float pix = sc[S_VIS + i*4], piy = sc[S_VIS + i*4 + 1], piz = sc[S_VIS + i*4 + 2];
    float pjx = sc[S_VIS + j*4], pjy = sc[S_VIS + j*4 + 1], pjz = sc[S_VIS + j*4 + 2];
    float mx = (pix + pjx)*0.5f, my = (piy + pjy)*0.5f, mz = (piz + pjz)*0.5f;
    float dxr = pix - mx, dyr = piy - my, dzr = piz - mz;
    float r2 = dxr*dxr + dyr*dyr + dzr*dzr;
    bool viol = false;
#pragma unroll
    for (int k = 0; k < 8; k++) {
      float ex = sc[S_VIS + k*4] - mx, ey = sc[S_VIS + k*4 + 1] - my, ez = sc[S_VIS + k*4 + 2] - mz;
      float d2 = ex*ex + ey*ey + ez*ez;
      viol |= (k != i) && (k != j) && (d2 < r2);
    }
    float adjv = (!viol && (i != j)) ? 1.f : 0.f;
    float ddx = pix - pjx, ddy = piy - pjy, ddz = piz - pjz;
    float dv = sqrtf(ddx*ddx + ddy*ddy + ddz*ddz + 1e-30f);

    // reduce n_edges and sum(dist*adj) over the 64 pairs (2 warps)
    float asum = adjv, dsum = adjv*dv;
#pragma unroll
    for (int m = 16; m; m >>= 1) {
      asum += __shfl_xor_sync(0xffffffffu, asum, m);
      dsum += __shfl_xor_sync(0xffffffffu, dsum, m);
    }
    int w = t >> 5;
    if ((t & 31) == 0) { sc[S_RED + w] = asum; sc[S_RED + 2 + w] = dsum; }
    __syncthreads();
    if (t == 0) {
      float ne = sc[S_RED] + sc[S_RED + 1];
      float ds = sc[S_RED + 2] + sc[S_RED + 3];
      sc[S_RED + 4] = ds / fmaxf(ne, 1.f);
    }
    __syncthreads();
    float ma = sc[S_RED + 4];
    sc[S_EAT  + i*9 + j] = (i == j) ? ma  : dv;
    sc[S_MASK + i*9 + j] = (i == j) ? 1.f : adjv;
    if (valid) out[3*Btot*24 + s*64 + t] = adjv;
  }
  __syncthreads();

  // ================= GATv2 layer 1 (x = latent) =================
  // xl -> A, xr -> B   (thread = channel)
  {
    float wl0 = ws[G1WL + t], wl1 = ws[G1WL + 64 + t], wl2 = ws[G1WL + 128 + t], bl = ws[G1BL + t];
    float wr0 = ws[G1WR + t], wr1 = ws[G1WR + 64 + t], wr2 = ws[G1WR + 128 + t], br = ws[G1BR + t];
#pragma unroll
    for (int n = 0; n < 8; n++) {
      float l0 = sc[S_LAT + n*4], l1 = sc[S_LAT + n*4 + 1], l2 = sc[S_LAT + n*4 + 2];
      sc[S_A + n*STRIDE + t] = fmaf(l0, wl0, fmaf(l1, wl1, fmaf(l2, wl2, bl)));
      sc[S_B + n*STRIDE + t] = fmaf(l0, wr0, fmaf(l1, wr1, fmaf(l2, wr2, br)));
    }
  }
  __syncthreads();
  // edge scores + masked softmax (thread = pair)
  {
    int i = t >> 3, j = t & 7;
    float eatv = sc[S_EAT + i*9 + j];
    float maskv = sc[S_MASK + i*9 + j];
    float acc = 0.f;
#pragma unroll 16
    for (int c = 0; c < 64; c++) {
      float h = sc[S_B + i*STRIDE + c] + sc[S_A + j*STRIDE + c] + eatv*ws[G1WE + c];
      h = (h < 0.f) ? 0.2f*h : h;
      acc = fmaf(h, ws[G1ATT + c], acc);
    }
    float ev = (maskv != 0.f) ? acc : -1e30f;
    float mxv = ev;
#pragma unroll
    for (int m = 4; m; m >>= 1) mxv = fmaxf(mxv, __shfl_xor_sync(0xffffffffu, mxv, m));
    float ex = __expf(ev - mxv);
    float sm = ex;
#pragma unroll
    for (int m = 4; m; m >>= 1) sm += __shfl_xor_sync(0xffffffffu, sm, m);
    sc[S_ALPHA + i*9 + j] = (ex / sm) * maskv;
  }
  __syncthreads();
  // aggregation -> B (relu)   (thread = channel)
  {
#pragma unroll
    for (int i = 0; i < 8; i++) {
      float acc = ws[G1BIAS + t];
#pragma unroll
      for (int j = 0; j < 8; j++) acc = fmaf(sc[S_ALPHA + i*9 + j], sc[S_A + j*STRIDE + t], acc);
      sc[S_B + i*STRIDE + t] = fmaxf(acc, 0.f);
    }
  }
  __syncthreads();

  // ================= GATv2 layer 2 (x = h1, 64 -> 3) =================
  if (t < 24) {
    int n = t / 3, l = t % 3;
    float a1 = ws[G2BL + l], a2 = ws[G2BR + l];
#pragma unroll 16
    for (int k = 0; k < 64; k++) {
      float h = sc[S_B + n*STRIDE + k];
      a1 = fmaf(h, ws[G2WL + k*3 + l], a1);
      a2 = fmaf(h, ws[G2WR + k*3 + l], a2);
    }
    sc[S_XL2 + n*4 + l] = a1;
    sc[S_XR2 + n*4 + l] = a2;
  }
  __syncthreads();
  {
    int i = t >> 3, j = t & 7;
    float eatv = sc[S_EAT + i*9 + j];
    float maskv = sc[S_MASK + i*9 + j];
    float acc = 0.f;
#pragma unroll
    for (int l = 0; l < 3; l++) {
      float h = sc[S_XR2 + i*4 + l] + sc[S_XL2 + j*4 + l] + eatv*ws[G2WE + l];
      h = (h < 0.f) ? 0.2f*h : h;
      acc = fmaf(h, ws[G2ATT + l], acc);
    }
    float ev = (maskv != 0.f) ? acc : -1e30f;
    float mxv = ev;
#pragma unroll
    for (int m = 4; m; m >>= 1) mxv = fmaxf(mxv, __shfl_xor_sync(0xffffffffu, mxv, m));
    float ex = __expf(ev - mxv);
    float sm = ex;
#pragma unroll
    for (int m = 4; m; m >>= 1) sm += __shfl_xor_sync(0xffffffffu, sm, m);
    sc[S_ALPHA + i*9 + j] = (ex / sm) * maskv;
  }
  __syncthreads();
  // aggregation + skip -> combined
  if (t < 24) {
    int n = t / 3, l = t % 3;
    float acc = ws[G2BIAS + l];
#pragma unroll
    for (int j = 0; j < 8; j++) acc = fmaf(sc[S_ALPHA + n*9 + j], sc[S_XL2 + j*4 + l], acc);
    float l0 = sc[S_LAT + n*4], l1 = sc[S_LAT + n*4 + 1], l2 = sc[S_LAT + n*4 + 2];
    acc += fmaf(l0, ws[SKW + l], fmaf(l1, ws[SKW + 3 + l], fmaf(l2, ws[SKW + 6 + l], ws[SKB + l])));
    sc[S_COMB + n*4 + l] = acc;
  }
  __syncthreads();

  // ================= decoder =================
  {
    float w0 = ws[DW1 + t], w1 = ws[DW1 + 64 + t], w2 = ws[DW1 + 128 + t], b = ws[DB1 + t];
#pragma unroll
    for (int n = 0; n < 8; n++) {
      float h = fmaf(sc[S_COMB + n*4], w0,
               fmaf(sc[S_COMB + n*4 + 1], w1,
               fmaf(sc[S_COMB + n*4 + 2], w2, b)));
      sc[S_A + n*STRIDE + t] = fmaxf(h, 0.f);
    }
  }
  __syncthreads();
  mlp64x64(sc + S_A, sc + S_B, ws + DW2, ws + DB2, t);
  __syncthreads();
  if (valid && t < 24) {
    int n = t / 3, f = t % 3;
    float acc = ws[DB3 + f];
#pragma unroll 16
    for (int k = 0; k < 64; k++) acc = fmaf(sc[S_B + n*STRIDE + k], ws[DW3 + k*3 + f], acc);
    out[Btot*24 + s*24 + t] = acc;  // rec
  }
}

extern "C" void kernel_launch(void* const* d_in, const int* in_sizes, int n_in,
                              void* d_out, int out_size)
{
  (void)n_in; (void)out_size;
  KParams kp;
  kp.x = (const float*)d_in[0];
  for (int i = 0; i < 28; i++) kp.w[i] = (const float*)d_in[i + 1];
  kp.B = in_sizes[0] / 8;

  cudaFuncSetAttribute(gae_kernel, cudaFuncAttributeMaxDynamicSharedMemorySize, SMEM_BYTES);
  int grid = (kp.B + SPB - 1) / SPB;
  gae_kernel<<<grid, THREADS, SMEM_BYTES>>>(kp, (float*)d_out);
}

// round 2
// speedup vs baseline: 2.0446x; 2.0446x over previous
#include <cuda_runtime.h>

#define SPB 16           // samples per block (1 warp per sample)
#define THREADS 512

// ---- weight offsets in shared (floats) ----
enum {
  EW1=0, EB1=192, EW2P=256, EB2P=4352, EW3=4416, EB3=4608,
  G1WL=4612, G1BL=4804, G1WR=4868, G1BR=5060,
  G1WE=5124, G1ATT=5188, G1BIAS=5252,
  G2WLT=5316, G2BL4=5508, G2WRT=5512, G2BR4=5704,
  G2WE4=5708, G2ATT4=5712, G2BIAS4=5716,
  SKW=5720, SKB=5732,
  DW1=5736, DB1=5928, DW2P=5992, DB2P=10088, DW3=10152, DB3=10344,
  WTOT=10348
};
// ---- per-sample scratch offsets (floats) ----
enum {
  SA=0, SB=512, SXL=1024, SXR=1632, SEAT=2240, SMSK=2304, SALPHA=2368,
  SLAT=2432, SVIS=2464, SCOMB=2496, SXL2=2528, SXR2=2560, SX=2592,
  SPER=2608
};

#define SMEM_FLOATS (WTOT + SPB*SPER)
#define SMEM_BYTES  (SMEM_FLOATS*4)

struct KParams {
  const float* x;
  const float* w[28];
  int B;
};

extern __shared__ float smem[];

__device__ __forceinline__ void cpy(float* dst, const float* src, int n, int tid) {
  for (int i = tid; i < n; i += THREADS) dst[i] = src[i];
}

// 8x64 @ 64x64 + relu. in: [k][n] stride 8. Wp: column-permuted [k][64].
// bp: permuted bias. thread: cg=t&15 (4 logical ch {16j+cg}), ng=t>>4 (nodes ng*4..+3)
__device__ __forceinline__ void mlp64(const float* __restrict__ in, float* __restrict__ ob,
                                      const float* __restrict__ Wp, const float* __restrict__ bp,
                                      int t)
{
  const int cg = t & 15, ng = t >> 4;
  float4 b4 = *(const float4*)&bp[4*cg];
  float4 A0 = make_float4(b4.x, b4.x, b4.x, b4.x);
  float4 A1 = make_float4(b4.y, b4.y, b4.y, b4.y);
  float4 A2 = make_float4(b4.z, b4.z, b4.z, b4.z);
  float4 A3 = make_float4(b4.w, b4.w, b4.w, b4.w);
  const float* ap = in + 4*ng;
  const float* wp = Wp + 4*cg;
#pragma unroll 8
  for (int k = 0; k < 64; k++) {
    float4 av = *(const float4*)&ap[k*8];
    float4 wv = *(const float4*)&wp[k*64];
    A0.x = fmaf(wv.x, av.x, A0.x); A0.y = fmaf(wv.x, av.y, A0.y);
    A0.z = fmaf(wv.x, av.z, A0.z); A0.w = fmaf(wv.x, av.w, A0.w);
    A1.x = fmaf(wv.y, av.x, A1.x); A1.y = fmaf(wv.y, av.y, A1.y);
    A1.z = fmaf(wv.y, av.z, A1.z); A1.w = fmaf(wv.y, av.w, A1.w);
    A2.x = fmaf(wv.z, av.x, A2.x); A2.y = fmaf(wv.z, av.y, A2.y);
    A2.z = fmaf(wv.z, av.z, A2.z); A2.w = fmaf(wv.z, av.w, A2.w);
    A3.x = fmaf(wv.w, av.x, A3.x); A3.y = fmaf(wv.w, av.y, A3.y);
    A3.z = fmaf(wv.w, av.z, A3.z); A3.w = fmaf(wv.w, av.w, A3.w);
  }
  A0.x = fmaxf(A0.x,0.f); A0.y = fmaxf(A0.y,0.f); A0.z = fmaxf(A0.z,0.f); A0.w = fmaxf(A0.w,0.f);
  A1.x = fmaxf(A1.x,0.f); A1.y = fmaxf(A1.y,0.f); A1.z = fmaxf(A1.z,0.f); A1.w = fmaxf(A1.w,0.f);
  A2.x = fmaxf(A2.x,0.f); A2.y = fmaxf(A2.y,0.f); A2.z = fmaxf(A2.z,0.f); A2.w = fmaxf(A2.w,0.f);
  A3.x = fmaxf(A3.x,0.f); A3.y = fmaxf(A3.y,0.f); A3.z = fmaxf(A3.z,0.f); A3.w = fmaxf(A3.w,0.f);
  *(float4*)&ob[cg*8      + 4*ng] = A0;
  *(float4*)&ob[(16+cg)*8 + 4*ng] = A1;
  *(float4*)&ob[(32+cg)*8 + 4*ng] = A2;
  *(float4*)&ob[(48+cg)*8 + 4*ng] = A3;
}

__device__ __forceinline__ float lrelu(float h) {
  return fmaxf(h, 0.f) + 0.2f*fminf(h, 0.f);
}

__global__ __launch_bounds__(THREADS, 1)
void gae2_kernel(KParams kp, float* __restrict__ out)
{
  float* ws = smem;
  const int tid = threadIdx.x;

  // ================= stage weights =================
  cpy(ws+EW1, kp.w[0], 192, tid); cpy(ws+EB1, kp.w[1], 64, tid);
  { const float* s = kp.w[2];
    for (int i = tid; i < 4096; i += THREADS) {
      int k = i >> 6, p = i & 63;
      ws[EW2P + i] = s[k*64 + 16*(p&3) + (p>>2)];
    } }
  { const float* s = kp.w[3];
    for (int i = tid; i < 64; i += THREADS) ws[EB2P + i] = s[16*(i&3) + (i>>2)]; }
  cpy(ws+EW3, kp.w[4], 192, tid);
  if (tid < 4) ws[EB3+tid] = (tid < 3) ? kp.w[5][tid] : 0.f;
  cpy(ws+G1WL, kp.w[6], 192, tid);  cpy(ws+G1BL, kp.w[7], 64, tid);
  cpy(ws+G1WR, kp.w[8], 192, tid);  cpy(ws+G1BR, kp.w[9], 64, tid);
  cpy(ws+G1WE, kp.w[10], 64, tid);  cpy(ws+G1ATT, kp.w[11], 64, tid);
  cpy(ws+G1BIAS, kp.w[12], 64, tid);
  { const float* wl = kp.w[13]; const float* wr = kp.w[15];
    for (int i = tid; i < 192; i += THREADS) {
      int l = i >> 6, k = i & 63;
      ws[G2WLT + i] = wl[k*3 + l];
      ws[G2WRT + i] = wr[k*3 + l];
    } }
  if (tid < 4) {
    ws[G2BL4 + tid]   = (tid < 3) ? kp.w[14][tid] : 0.f;
    ws[G2BR4 + tid]   = (tid < 3) ? kp.w[16][tid] : 0.f;
    ws[G2WE4 + tid]   = (tid < 3) ? kp.w[17][tid] : 0.f;
    ws[G2ATT4 + tid]  = (tid < 3) ? kp.w[18][tid] : 0.f;
    ws[G2BIAS4 + tid] = (tid < 3) ? kp.w[19][tid] : 0.f;
  }
  if (tid < 12) ws[SKW+tid] = (tid < 9) ? kp.w[20][tid] : 0.f;
  if (tid < 4)  ws[SKB+tid] = (tid < 3) ? kp.w[21][tid] : 0.f;
  cpy(ws+DW1, kp.w[22], 192, tid); cpy(ws+DB1, kp.w[23], 64, tid);
  { const float* s = kp.w[24];
    for (int i = tid; i < 4096; i += THREADS) {
      int k = i >> 6, p = i & 63;
      ws[DW2P + i] = s[k*64 + 16*(p&3) + (p>>2)];
    } }
  { const float* s = kp.w[25];
    for (int i = tid; i < 64; i += THREADS) ws[DB2P + i] = s[16*(i&3) + (i>>2)]; }
  cpy(ws+DW3, kp.w[26], 192, tid);
  if (tid < 4) ws[DB3+tid] = (tid < 3) ? kp.w[27][tid] : 0.f;

  const int g = tid >> 5;
  const int t = tid & 31;
  float* sc = smem + WTOT + g*SPER;
  const int Btot = kp.B;
  const int s = blockIdx.x*SPB + g;

  if (s < Btot && t < 8) sc[SX + t] = kp.x[s*8 + t];
  __syncthreads();
  if (s >= Btot) return;

  const int n3 = t / 3, l3 = t - n3*3;    // (node, latent-dim) map for t<24 phases

  // ================= encoder L1 (3->64) =================
  {
    float wn1 = ws[EW1+64+t],    wx1 = ws[EW1+128+t],    bb1 = ws[EB1+t];
    float wn2 = ws[EW1+64+t+32], wx2 = ws[EW1+128+t+32], bb2 = ws[EB1+t+32];
    float va[8], vb[8];
#pragma unroll
    for (int n = 0; n < 8; n++) {
      float xn = sc[SX + n];
      va[n] = fmaxf(fmaf(xn, wx1, fmaf((float)n, wn1, bb1)), 0.f);
      vb[n] = fmaxf(fmaf(xn, wx2, fmaf((float)n, wn2, bb2)), 0.f);
    }
    *(float4*)&sc[SA + t*8]          = make_float4(va[0],va[1],va[2],va[3]);
    *(float4*)&sc[SA + t*8 + 4]      = make_float4(va[4],va[5],va[6],va[7]);
    *(float4*)&sc[SA + (t+32)*8]     = make_float4(vb[0],vb[1],vb[2],vb[3]);
    *(float4*)&sc[SA + (t+32)*8 + 4] = make_float4(vb[4],vb[5],vb[6],vb[7]);
  }
  __syncwarp();

  // ================= encoder L2 (64x64) =================
  mlp64(sc + SA, sc + SB, ws + EW2P, ws + EB2P, t);
  __syncwarp();

  // ================= encoder L3 (64->3) =================
  if (t < 24) {
    float acc = ws[EB3 + l3];
#pragma unroll 16
    for (int k = 0; k < 64; k++)
      acc = fmaf(sc[SB + k*8 + n3], ws[EW3 + k*3 + l3], acc);
    sc[SLAT + n3*4 + l3] = acc;
  }
  __syncwarp();

  // ================= normalize -> vis  (lane = l*8+n) =================
  {
    int ln_l = t >> 3, ln_n = t & 7;     // lanes 24..31 compute garbage, don't store
    float v = sc[SLAT + ln_n*4 + ((ln_l < 3) ? ln_l : 0)];
    float sm = v;
    sm += __shfl_xor_sync(0xffffffffu, sm, 1);
    sm += __shfl_xor_sync(0xffffffffu, sm, 2);
    sm += __shfl_xor_sync(0xffffffffu, sm, 4);
    float c = v - sm*0.125f;
    float vv = c*c;
    vv += __shfl_xor_sync(0xffffffffu, vv, 1);
    vv += __shfl_xor_sync(0xffffffffu, vv, 2);
    vv += __shfl_xor_sync(0xffffffffu, vv, 4);
    float inv = 1.f / (sqrtf(vv * (1.f/7.f)) + 1e-8f);
    float visv = c*inv;
    if (t < 24) {
      sc[SVIS + ln_n*4 + ln_l] = visv;
      out[2*Btot*24 + s*24 + ln_n*3 + ln_l] = visv;      // vis output
      float xpv = (l3 == 0) ? 0.f : ((l3 == 1) ? (float)n3 : sc[SX + n3]);
      out[s*24 + t] = xpv;                               // xp output
    }
  }
  __syncwarp();

  // ================= Gabriel graph (2 pairs per lane: p=t, p=t+32) =================
  {
    float4 Pv[8];
#pragma unroll
    for (int n = 0; n < 8; n++) Pv[n] = *(const float4*)&sc[SVIS + n*4];
    int i0 = t >> 3, j0 = t & 7;
    int i1 = (t + 32) >> 3, j1 = t & 7;          // (t+32)&7 == t&7
    float4 pi0 = *(const float4*)&sc[SVIS + i0*4];
    float4 pj0 = *(const float4*)&sc[SVIS + j0*4];
    float4 pi1 = *(const float4*)&sc[SVIS + i1*4];
    float4 pj1 = pj0;
    float a0, d0, a1, d1;
    {
      float mx=(pi0.x+pj0.x)*0.5f, my=(pi0.y+pj0.y)*0.5f, mz=(pi0.z+pj0.z)*0.5f;
      float rx=pi0.x-mx, ry=pi0.y-my, rz=pi0.z-mz;
      float r2 = rx*rx+ry*ry+rz*rz;
      bool viol = false;
#pragma unroll
      for (int k = 0; k < 8; k++) {
        float ex=Pv[k].x-mx, ey=Pv[k].y-my, ez=Pv[k].z-mz;
        float d2 = ex*ex+ey*ey+ez*ez;
        viol |= (k != i0) && (k != j0) && (d2 < r2);
      }
      a0 = (!viol && (i0 != j0)) ? 1.f : 0.f;
      float dx=pi0.x-pj0.x, dy=pi0.y-pj0.y, dz=pi0.z-pj0.z;
      d0 = sqrtf(dx*dx+dy*dy+dz*dz + 1e-30f);
    }
    {
      float mx=(pi1.x+pj1.x)*0.5f, my=(pi1.y+pj1.y)*0.5f, mz=(pi1.z+pj1.z)*0.5f;
      float rx=pi1.x-mx, ry=pi1.y-my, rz=pi1.z-mz;
      float r2 = rx*rx+ry*ry+rz*rz;
      bool viol = false;
#pragma unroll
      for (int k = 0; k < 8; k++) {
        float ex=Pv[k].x-mx, ey=Pv[k].y-my, ez=Pv[k].z-mz;
        float d2 = ex*ex+ey*ey+ez*ez;
        viol |= (k != i1) && (k != j1) && (d2 < r2);
      }
      a1 = (!viol && (i1 != j1)) ? 1.f : 0.f;
      float dx=pi1.x-pj1.x, dy=pi1.y-pj1.y, dz=pi1.z-pj1.z;
      d1 = sqrtf(dx*dx+dy*dy+dz*dz + 1e-30f);
    }
    float as = a0 + a1, ds = a0*d0 + a1*d1;
#pragma unroll
    for (int m = 16; m; m >>= 1) {
      as += __shfl_xor_sync(0xffffffffu, as, m);
      ds += __shfl_xor_sync(0xffffffffu, ds, m);
    }
    float ma = ds / fmaxf(as, 1.f);
    sc[SEAT + t]      = (i0 == j0) ? ma  : d0;
    sc[SEAT + t + 32] = (i1 == j1) ? ma  : d1;
    sc[SMSK + t]      = (i0 == j0) ? 1.f : a0;
    sc[SMSK + t + 32] = (i1 == j1) ? 1.f : a1;
    out[3*Btot*24 + s*64 + t]      = a0;                 // adj output
    out[3*Btot*24 + s*64 + t + 32] = a1;
  }

  // ================= GAT1 linear (3->64 xl, xr)  [n][c] stride 76 =================
  {
    float wl0a=ws[G1WL+t],    wl1a=ws[G1WL+64+t],    wl2a=ws[G1WL+128+t],    bla=ws[G1BL+t];
    float wl0b=ws[G1WL+t+32], wl1b=ws[G1WL+64+t+32], wl2b=ws[G1WL+128+t+32], blb=ws[G1BL+t+32];
    float wr0a=ws[G1WR+t],    wr1a=ws[G1WR+64+t],    wr2a=ws[G1WR+128+t],    bra=ws[G1BR+t];
    float wr0b=ws[G1WR+t+32], wr1b=ws[G1WR+64+t+32], wr2b=ws[G1WR+128+t+32], brb=ws[G1BR+t+32];
#pragma unroll
    for (int n = 0; n < 8; n++) {
      float4 la = *(const float4*)&sc[SLAT + n*4];
      sc[SXL + n*76 + t]      = fmaf(la.x, wl0a, fmaf(la.y, wl1a, fmaf(la.z, wl2a, bla)));
      sc[SXL + n*76 + t + 32] = fmaf(la.x, wl0b, fmaf(la.y, wl1b, fmaf(la.z, wl2b, blb)));
      sc[SXR + n*76 + t]      = fmaf(la.x, wr0a, fmaf(la.y, wr1a, fmaf(la.z, wr2a, bra)));
      sc[SXR + n*76 + t + 32] = fmaf(la.x, wr0b, fmaf(la.y, wr1b, fmaf(la.z, wr2b, brb)));
    }
  }
  __syncwarp();

  // ================= GAT1 edge scores + softmax (2 pairs: p=2t, 2t+1) =================
  {
    const int i = t >> 2;
    const int jj = (t & 3) * 2;
    const float* xr = sc + SXR + i*76;
    const float* xa = sc + SXL + jj*76;
    float2 ea = *(const float2*)&sc[SEAT + 2*t];
    float2 mk = *(const float2*)&sc[SMSK + 2*t];
    float acc0 = 0.f, acc1 = 0.f;
#pragma unroll 8
    for (int c = 0; c < 64; c += 4) {
      float4 r  = *(const float4*)&xr[c];
      float4 l0 = *(const float4*)&xa[c];
      float4 l1 = *(const float4*)&xa[c + 76];
      float4 we = *(const float4*)&ws[G1WE + c];
      float4 at = *(const float4*)&ws[G1ATT + c];
      acc0 = fmaf(lrelu(fmaf(ea.x, we.x, r.x) + l0.x), at.x, acc0);
      acc1 = fmaf(lrelu(fmaf(ea.y, we.x, r.x) + l1.x), at.x, acc1);
      acc0 = fmaf(lrelu(fmaf(ea.x, we.y, r.y) + l0.y), at.y, acc0);
      acc1 = fmaf(lrelu(fmaf(ea.y, we.y, r.y) + l1.y), at.y, acc1);
      acc0 = fmaf(lrelu(fmaf(ea.x, we.z, r.z) + l0.z), at.z, acc0);
      acc1 = fmaf(lrelu(fmaf(ea.y, we.z, r.z) + l1.z), at.z, acc1);
      acc0 = fmaf(lrelu(fmaf(ea.x, we.w, r.w) + l0.w), at.w, acc0);
      acc1 = fmaf(lrelu(fmaf(ea.y, we.w, r.w) + l1.w), at.w, acc1);
    }
    float e0 = (mk.x != 0.f) ? acc0 : -1e30f;
    float e1 = (mk.y != 0.f) ? acc1 : -1e30f;
    float m = fmaxf(e0, e1);
    m = fmaxf(m, __shfl_xor_sync(0xffffffffu, m, 1));
    m = fmaxf(m, __shfl_xor_sync(0xffffffffu, m, 2));
    float x0 = __expf(e0 - m), x1 = __expf(e1 - m);
    float sden = x0 + x1;
    sden += __shfl_xor_sync(0xffffffffu, sden, 1);
    sden += __shfl_xor_sync(0xffffffffu, sden, 2);
    float inv = 1.f / sden;
    *(float2*)&sc[SALPHA + 2*t] = make_float2(x0*inv*mk.x, x1*inv*mk.y);
  }
  __syncwarp();

  // ================= GAT1 aggregation -> h1 (into SXR), relu =================
  {
    float acc1[8], acc2[8];
    float b1 = ws[G1BIAS + t], b2 = ws[G1BIAS + t + 32];
#pragma unroll
    for (int i = 0; i < 8; i++) { acc1[i] = b1; acc2[i] = b2; }
#pragma unroll
    for (int j = 0; j < 8; j++) {
      float xv1 = sc[SXL + j*76 + t];
      float xv2 = sc[SXL + j*76 + t + 32];
#pragma unroll
      for (int i = 0; i < 8; i++) {
        float al = sc[SALPHA + i*8 + j];
        acc1[i] = fmaf(al, xv1, acc1[i]);
        acc2[i] = fmaf(al, xv2, acc2[i]);
      }
    }
    __syncwarp();   // all edge-phase reads of SXR done before overwrite
#pragma unroll
    for (int i = 0; i < 8; i++) {
      sc[SXR + i*76 + t]      = fmaxf(acc1[i], 0.f);
      sc[SXR + i*76 + t + 32] = fmaxf(acc2[i], 0.f);
    }
  }
  __syncwarp();

  // ================= GAT2 linear (64->3 xl2, xr2) =================
  if (t < 24) {
    float a1 = ws[G2BL4 + l3], a2 = ws[G2BR4 + l3];
    const float* h1p = sc + SXR + n3*76;
#pragma unroll
    for (int c = 0; c < 64; c += 4) {
      float4 h  = *(const float4*)&h1p[c];
      float4 wl = *(const float4*)&ws[G2WLT + l3*64 + c];
      float4 wr = *(const float4*)&ws[G2WRT + l3*64 + c];
      a1 = fmaf(h.x, wl.x, fmaf(h.y, wl.y, fmaf(h.z, wl.z, fmaf(h.w, wl.w, a1))));
      a2 = fmaf(h.x, wr.x, fmaf(h.y, wr.y, fmaf(h.z, wr.z, fmaf(h.w, wr.w, a2))));
    }
    sc[SXL2 + n3*4 + l3] = a1;
    sc[SXR2 + n3*4 + l3] = a2;
  }
  __syncwarp();

  // ================= GAT2 edge scores + softmax =================
  {
    const int i = t >> 2;
    const int jj = (t & 3) * 2;
    float4 r   = *(const float4*)&sc[SXR2 + i*4];
    float4 l0  = *(const float4*)&sc[SXL2 + jj*4];
    float4 l1  = *(const float4*)&sc[SXL2 + (jj+1)*4];
    float4 we  = *(const float4*)&ws[G2WE4];
    float4 at  = *(const float4*)&ws[G2ATT4];
    float2 ea = *(const float2*)&sc[SEAT + 2*t];
    float2 mk = *(const float2*)&sc[SMSK + 2*t];
    float acc0 = 0.f, acc1 = 0.f;
    acc0 = fmaf(lrelu(fmaf(ea.x, we.x, r.x) + l0.x), at.x, acc0);
    acc1 = fmaf(lrelu(fmaf(ea.y, we.x, r.x) + l1.x), at.x, acc1);
    acc0 = fmaf(lrelu(fmaf(ea.x, we.y, r.y) + l0.y), at.y, acc0);
    acc1 = fmaf(lrelu(fmaf(ea.y, we.y, r.y) + l1.y), at.y, acc1);
    acc0 = fmaf(lrelu(fmaf(ea.x, we.z, r.z) + l0.z), at.z, acc0);
    acc1 = fmaf(lrelu(fmaf(ea.y, we.z, r.z) + l1.z), at.z, acc1);
    float e0 = (mk.x != 0.f) ? acc0 : -1e30f;
    float e1 = (mk.y != 0.f) ? acc1 : -1e30f;
    float m = fmaxf(e0, e1);
    m = fmaxf(m, __shfl_xor_sync(0xffffffffu, m, 1));
    m = fmaxf(m, __shfl_xor_sync(0xffffffffu, m, 2));
    float x0 = __expf(e0 - m), x1 = __expf(e1 - m);
    float sden = x0 + x1;
    sden += __shfl_xor_sync(0xffffffffu, sden, 1);
    sden += __shfl_xor_sync(0xffffffffu, sden, 2);
    float inv = 1.f / sden;
    *(float2*)&sc[SALPHA + 2*t] = make_float2(x0*inv*mk.x, x1*inv*mk.y);
  }
  __syncwarp();

  // ================= GAT2 aggregation + skip -> combined =================
  if (t < 24) {
    float acc = ws[G2BIAS4 + l3];
#pragma unroll
    for (int j = 0; j < 8; j++)
      acc = fmaf(sc[SALPHA + n3*8 + j], sc[SXL2 + j*4 + l3], acc);
    float4 la = *(const float4*)&sc[SLAT + n3*4];
    acc += fmaf(la.x, ws[SKW + l3],
           fmaf(la.y, ws[SKW + 3 + l3],
           fmaf(la.z, ws[SKW + 6 + l3], ws[SKB + l3])));
    sc[SCOMB + n3*4 + l3] = acc;
  }
  __syncwarp();

  // ================= decoder L1 (3->64) =================
  {
    float w0a=ws[DW1+t],    w1a=ws[DW1+64+t],    w2a=ws[DW1+128+t],    ba=ws[DB1+t];
    float w0b=ws[DW1+t+32], w1b=ws[DW1+64+t+32], w2b=ws[DW1+128+t+32], bb=ws[DB1+t+32];
    float va[8], vb[8];
#pragma unroll
    for (int n = 0; n < 8; n++) {
      float4 cm = *(const float4*)&sc[SCOMB + n*4];
      va[n] = fmaxf(fmaf(cm.x, w0a, fmaf(cm.y, w1a, fmaf(cm.z, w2a, ba))), 0.f);
      vb[n] = fmaxf(fmaf(cm.x, w0b, fmaf(cm.y, w1b, fmaf(cm.z, w2b, bb))), 0.f);
    }
    *(float4*)&sc[SA + t*8]          = make_float4(va[0],va[1],va[2],va[3]);
    *(float4*)&sc[SA + t*8 + 4]      = make_float4(va[4],va[5],va[6],va[7]);
    *(float4*)&sc[SA + (t+32)*8]     = make_float4(vb[0],vb[1],vb[2],vb[3]);
    *(float4*)&sc[SA + (t+32)*8 + 4] = make_float4(vb[4],vb[5],vb[6],vb[7]);
  }
  __syncwarp();

  // ================= decoder L2 (64x64) =================
  mlp64(sc + SA, sc + SB, ws + DW2P, ws + DB2P, t);
  __syncwarp();

  // ================= decoder L3 (64->3) -> rec output =================
  if (t < 24) {
    float acc = ws[DB3 + l3];
#pragma unroll 16
    for (int k = 0; k < 64; k++)
      acc = fmaf(sc[SB + k*8 + n3], ws[DW3 + k*3 + l3], acc);
    out[Btot*24 + s*24 + t] = acc;
  }
}

extern "C" void kernel_launch(void* const* d_in, const int* in_sizes, int n_in,
                              void* d_out, int out_size)
{
  (void)n_in; (void)out_size;
  KParams kp;
  kp.x = (const float*)d_in[0];
  for (int i = 0; i < 28; i++) kp.w[i] = (const float*)d_in[i + 1];
  kp.B = in_sizes[0] / 8;

  cudaFuncSetAttribute(gae2_kernel, cudaFuncAttributeMaxDynamicSharedMemorySize, SMEM_BYTES);
  int grid = (kp.B + SPB - 1) / SPB;
  gae2_kernel<<<grid, THREADS, SMEM_BYTES>>>(kp, (float*)d_out);
}

// round 3
// speedup vs baseline: 2.1545x; 1.0538x over previous
#include <cuda_runtime.h>

#define SPB 12           // samples per block (1 warp per sample)
#define THREADS 384

// ---- weight offsets in shared (floats) ----
enum {
  EW1=0, EB1=192, EW2P=256, EB2P=4352, EW3=4416, EB3=4608,
  G1WL=4612, G1BL=4804, G1WR=4868, G1BR=5060,
  G1WE=5124, G1ATT=5188, G1BIAS=5252,
  G2WLT=5316, G2BL4=5508, G2WRT=5512, G2BR4=5704,
  G2WE4=5708, G2ATT4=5712, G2BIAS4=5716,
  SKW=5720, SKB=5732,
  DW1=5736, DB1=5928, DW2P=5992, DB2P=10088, DW3=10152, DB3=10344,
  WTOT=10348
};
// ---- per-sample scratch offsets (floats); SA/SB overlap SXL/SXR ----
// U region [0,1088): SA=[0,512) SB=[544,1056) | SXL=[0,544) SXR=[544,1088)
enum {
  SA=0, SB=544, SXL=0, SXR=544,
  SEAT=1088, SMSK=1152, SALPHA=1216,
  SLAT=1280, SVIS=1312, SCOMB=1344, SXL2=1376, SXR2=1408, SX=1440,
  SPER=1456
};

#define SMEM_FLOATS (WTOT + SPB*SPER)
#define SMEM_BYTES  (SMEM_FLOATS*4)   // 111,280 bytes -> 2 blocks/SM

struct KParams {
  const float* x;
  const float* w[28];
  int B;
};

extern __shared__ float smem[];

__device__ __forceinline__ void cpy(float* dst, const float* src, int n, int tid) {
  for (int i = tid; i < n; i += THREADS) dst[i] = src[i];
}

// 8x64 @ 64x64 + relu. in: [k][n] stride 8. Wp: column-permuted [k][64].
// bp: permuted bias. thread: cg=t&15 (4 logical ch {16j+cg}), ng=t>>4 (nodes ng*4..+3)
__device__ __forceinline__ void mlp64(const float* __restrict__ in, float* __restrict__ ob,
                                      const float* __restrict__ Wp, const float* __restrict__ bp,
                                      int t)
{
  const int cg = t & 15, ng = t >> 4;
  float4 b4 = *(const float4*)&bp[4*cg];
  float4 A0 = make_float4(b4.x, b4.x, b4.x, b4.x);
  float4 A1 = make_float4(b4.y, b4.y, b4.y, b4.y);
  float4 A2 = make_float4(b4.z, b4.z, b4.z, b4.z);
  float4 A3 = make_float4(b4.w, b4.w, b4.w, b4.w);
  const float* ap = in + 4*ng;
  const float* wp = Wp + 4*cg;
#pragma unroll 8
  for (int k = 0; k < 64; k++) {
    float4 av = *(const float4*)&ap[k*8];
    float4 wv = *(const float4*)&wp[k*64];
    A0.x = fmaf(wv.x, av.x, A0.x); A0.y = fmaf(wv.x, av.y, A0.y);
    A0.z = fmaf(wv.x, av.z, A0.z); A0.w = fmaf(wv.x, av.w, A0.w);
    A1.x = fmaf(wv.y, av.x, A1.x); A1.y = fmaf(wv.y, av.y, A1.y);
    A1.z = fmaf(wv.y, av.z, A1.z); A1.w = fmaf(wv.y, av.w, A1.w);
    A2.x = fmaf(wv.z, av.x, A2.x); A2.y = fmaf(wv.z, av.y, A2.y);
    A2.z = fmaf(wv.z, av.z, A2.z); A2.w = fmaf(wv.z, av.w, A2.w);
    A3.x = fmaf(wv.w, av.x, A3.x); A3.y = fmaf(wv.w, av.y, A3.y);
    A3.z = fmaf(wv.w, av.z, A3.z); A3.w = fmaf(wv.w, av.w, A3.w);
  }
  A0.x = fmaxf(A0.x,0.f); A0.y = fmaxf(A0.y,0.f); A0.z = fmaxf(A0.z,0.f); A0.w = fmaxf(A0.w,0.f);
  A1.x = fmaxf(A1.x,0.f); A1.y = fmaxf(A1.y,0.f); A1.z = fmaxf(A1.z,0.f); A1.w = fmaxf(A1.w,0.f);
  A2.x = fmaxf(A2.x,0.f); A2.y = fmaxf(A2.y,0.f); A2.z = fmaxf(A2.z,0.f); A2.w = fmaxf(A2.w,0.f);
  A3.x = fmaxf(A3.x,0.f); A3.y = fmaxf(A3.y,0.f); A3.z = fmaxf(A3.z,0.f); A3.w = fmaxf(A3.w,0.f);
  *(float4*)&ob[cg*8      + 4*ng] = A0;
  *(float4*)&ob[(16+cg)*8 + 4*ng] = A1;
  *(float4*)&ob[(32+cg)*8 + 4*ng] = A2;
  *(float4*)&ob[(48+cg)*8 + 4*ng] = A3;
}

__device__ __forceinline__ float lrelu(float h) {
  return fmaxf(h, 0.f) + 0.2f*fminf(h, 0.f);
}

__global__ __launch_bounds__(THREADS, 2)
void gae3_kernel(KParams kp, float* __restrict__ out)
{
  float* ws = smem;
  const int tid = threadIdx.x;

  // ================= stage weights (coalesced LDG, permuted STS) =================
  cpy(ws+EW1, kp.w[0], 192, tid); cpy(ws+EB1, kp.w[1], 64, tid);
  { const float* src = kp.w[2];
    for (int i = tid; i < 4096; i += THREADS) {
      int k = i >> 6, c = i & 63;
      ws[EW2P + k*64 + ((c & 15)*4 + (c >> 4))] = src[i];
    } }
  { const float* src = kp.w[3];
    for (int i = tid; i < 64; i += THREADS)
      ws[EB2P + (i & 15)*4 + (i >> 4)] = src[i]; }
  cpy(ws+EW3, kp.w[4], 192, tid);
  if (tid < 4) ws[EB3+tid] = (tid < 3) ? kp.w[5][tid] : 0.f;
  cpy(ws+G1WL, kp.w[6], 192, tid);  cpy(ws+G1BL, kp.w[7], 64, tid);
  cpy(ws+G1WR, kp.w[8], 192, tid);  cpy(ws+G1BR, kp.w[9], 64, tid);
  cpy(ws+G1WE, kp.w[10], 64, tid);  cpy(ws+G1ATT, kp.w[11], 64, tid);
  cpy(ws+G1BIAS, kp.w[12], 64, tid);
  { const float* wl = kp.w[13]; const float* wr = kp.w[15];
    for (int i = tid; i < 192; i += THREADS) {
      int k = i / 3, l = i - k*3;          // coalesced read of [k][l]
      ws[G2WLT + l*64 + k] = wl[i];
      ws[G2WRT + l*64 + k] = wr[i];
    } }
  if (tid < 4) {
    ws[G2BL4 + tid]   = (tid < 3) ? kp.w[14][tid] : 0.f;
    ws[G2BR4 + tid]   = (tid < 3) ? kp.w[16][tid] : 0.f;
    ws[G2WE4 + tid]   = (tid < 3) ? kp.w[17][tid] : 0.f;
    ws[G2ATT4 + tid]  = (tid < 3) ? kp.w[18][tid] : 0.f;
    ws[G2BIAS4 + tid] = (tid < 3) ? kp.w[19][tid] : 0.f;
  }
  if (tid < 12) ws[SKW+tid] = (tid < 9) ? kp.w[20][tid] : 0.f;
  if (tid < 4)  ws[SKB+tid] = (tid < 3) ? kp.w[21][tid] : 0.f;
  cpy(ws+DW1, kp.w[22], 192, tid); cpy(ws+DB1, kp.w[23], 64, tid);
  { const float* src = kp.w[24];
    for (int i = tid; i < 4096; i += THREADS) {
      int k = i >> 6, c = i & 63;
      ws[DW2P + k*64 + ((c & 15)*4 + (c >> 4))] = src[i];
    } }
  { const float* src = kp.w[25];
    for (int i = tid; i < 64; i += THREADS)
      ws[DB2P + (i & 15)*4 + (i >> 4)] = src[i]; }
  cpy(ws+DW3, kp.w[26], 192, tid);
  if (tid < 4) ws[DB3+tid] = (tid < 3) ? kp.w[27][tid] : 0.f;

  const int g = tid >> 5;
  const int t = tid & 31;
  float* sc = smem + WTOT + g*SPER;
  const int Btot = kp.B;
  const int s = blockIdx.x*SPB + g;

  if (s < Btot && t < 8) sc[SX + t] = kp.x[s*8 + t];
  __syncthreads();
  if (s >= Btot) return;

  const int n3 = t / 3, l3 = t - n3*3;    // (node, latent-dim) map for t<24 phases

  // ================= encoder L1 (3->64) =================
  {
    float wn1 = ws[EW1+64+t],    wx1 = ws[EW1+128+t],    bb1 = ws[EB1+t];
    float wn2 = ws[EW1+64+t+32], wx2 = ws[EW1+128+t+32], bb2 = ws[EB1+t+32];
    float va[8], vb[8];
#pragma unroll
    for (int n = 0; n < 8; n++) {
      float xn = sc[SX + n];
      va[n] = fmaxf(fmaf(xn, wx1, fmaf((float)n, wn1, bb1)), 0.f);
      vb[n] = fmaxf(fmaf(xn, wx2, fmaf((float)n, wn2, bb2)), 0.f);
    }
    *(float4*)&sc[SA + t*8]          = make_float4(va[0],va[1],va[2],va[3]);
    *(float4*)&sc[SA + t*8 + 4]      = make_float4(va[4],va[5],va[6],va[7]);
    *(float4*)&sc[SA + (t+32)*8]     = make_float4(vb[0],vb[1],vb[2],vb[3]);
    *(float4*)&sc[SA + (t+32)*8 + 4] = make_float4(vb[4],vb[5],vb[6],vb[7]);
  }
  __syncwarp();

  // ================= encoder L2 (64x64) =================
  mlp64(sc + SA, sc + SB, ws + EW2P, ws + EB2P, t);
  __syncwarp();

  // ================= encoder L3 (64->3) =================
  if (t < 24) {
    float acc = ws[EB3 + l3];
#pragma unroll 16
    for (int k = 0; k < 64; k++)
      acc = fmaf(sc[SB + k*8 + n3], ws[EW3 + k*3 + l3], acc);
    sc[SLAT + n3*4 + l3] = acc;
  }
  __syncwarp();

  // ================= normalize -> vis  (lane = l*8+n) =================
  {
    int ln_l = t >> 3, ln_n = t & 7;     // lanes 24..31 compute garbage, don't store
    float v = sc[SLAT + ln_n*4 + ((ln_l < 3) ? ln_l : 0)];
    float sm = v;
    sm += __shfl_xor_sync(0xffffffffu, sm, 1);
    sm += __shfl_xor_sync(0xffffffffu, sm, 2);
    sm += __shfl_xor_sync(0xffffffffu, sm, 4);
    float c = v - sm*0.125f;
    float vv = c*c;
    vv += __shfl_xor_sync(0xffffffffu, vv, 1);
    vv += __shfl_xor_sync(0xffffffffu, vv, 2);
    vv += __shfl_xor_sync(0xffffffffu, vv, 4);
    float inv = 1.f / (sqrtf(vv * (1.f/7.f)) + 1e-8f);
    float visv = c*inv;
    if (t < 24) {
      sc[SVIS + ln_n*4 + ln_l] = visv;
      out[2*Btot*24 + s*24 + ln_n*3 + ln_l] = visv;      // vis output
      float xpv = (l3 == 0) ? 0.f : ((l3 == 1) ? (float)n3 : sc[SX + n3]);
      out[s*24 + t] = xpv;                               // xp output
    }
  }
  __syncwarp();

  // ================= Gabriel graph (2 pairs per lane: p=t, p=t+32) =================
  {
    float4 Pv[8];
#pragma unroll
    for (int n = 0; n < 8; n++) Pv[n] = *(const float4*)&sc[SVIS + n*4];
    int i0 = t >> 3, j0 = t & 7;
    int i1 = (t + 32) >> 3;
    float4 pi0 = Pv[i0];
    float4 pj0 = Pv[j0];
    float4 pi1 = Pv[i1];
    float a0, d0, a1, d1;
    {
      float mx=(pi0.x+pj0.x)*0.5f, my=(pi0.y+pj0.y)*0.5f, mz=(pi0.z+pj0.z)*0.5f;
      float rx=pi0.x-mx, ry=pi0.y-my, rz=pi0.z-mz;
      float r2 = rx*rx+ry*ry+rz*rz;
      bool viol = false;
#pragma unroll
      for (int k = 0; k < 8; k++) {
        float ex=Pv[k].x-mx, ey=Pv[k].y-my, ez=Pv[k].z-mz;
        float d2 = ex*ex+ey*ey+ez*ez;
        viol |= (k != i0) && (k != j0) && (d2 < r2);
      }
      a0 = (!viol && (i0 != j0)) ? 1.f : 0.f;
      float dx=pi0.x-pj0.x, dy=pi0.y-pj0.y, dz=pi0.z-pj0.z;
      d0 = sqrtf(dx*dx+dy*dy+dz*dz + 1e-30f);
    }
    {
      float mx=(pi1.x+pj0.x)*0.5f, my=(pi1.y+pj0.y)*0.5f, mz=(pi1.z+pj0.z)*0.5f;
      float rx=pi1.x-mx, ry=pi1.y-my, rz=pi1.z-mz;
      float r2 = rx*rx+ry*ry+rz*rz;
      bool viol = false;
#pragma unroll
      for (int k = 0; k < 8; k++) {
        float ex=Pv[k].x-mx, ey=Pv[k].y-my, ez=Pv[k].z-mz;
        float d2 = ex*ex+ey*ey+ez*ez;
        viol |= (k != i1) && (k != j0) && (d2 < r2);
      }
      a1 = (!viol && (i1 != j0)) ? 1.f : 0.f;
      float dx=pi1.x-pj0.x, dy=pi1.y-pj0.y, dz=pi1.z-pj0.z;
      d1 = sqrtf(dx*dx+dy*dy+dz*dz + 1e-30f);
    }
    float as = a0 + a1, ds = a0*d0 + a1*d1;
#pragma unroll
    for (int m = 16; m; m >>= 1) {
      as += __shfl_xor_sync(0xffffffffu, as, m);
      ds += __shfl_xor_sync(0xffffffffu, ds, m);
    }
    float ma = ds / fmaxf(as, 1.f);
    sc[SEAT + t]      = (i0 == j0) ? ma  : d0;
    sc[SEAT + t + 32] = (i1 == j0) ? ma  : d1;
    sc[SMSK + t]      = (i0 == j0) ? 1.f : a0;
    sc[SMSK + t + 32] = (i1 == j0) ? 1.f : a1;
    out[3*Btot*24 + s*64 + t]      = a0;                 // adj output
    out[3*Btot*24 + s*64 + t + 32] = a1;
  }

  // ================= GAT1 linear (3->64 xl, xr)  [n][c] stride 68 =================
  {
    float wl0a=ws[G1WL+t],    wl1a=ws[G1WL+64+t],    wl2a=ws[G1WL+128+t],    bla=ws[G1BL+t];
    float wl0b=ws[G1WL+t+32], wl1b=ws[G1WL+64+t+32], wl2b=ws[G1WL+128+t+32], blb=ws[G1BL+t+32];
    float wr0a=ws[G1WR+t],    wr1a=ws[G1WR+64+t],    wr2a=ws[G1WR+128+t],    bra=ws[G1BR+t];
    float wr0b=ws[G1WR+t+32], wr1b=ws[G1WR+64+t+32], wr2b=ws[G1WR+128+t+32], brb=ws[G1BR+t+32];
#pragma unroll
    for (int n = 0; n < 8; n++) {
      float4 la = *(const float4*)&sc[SLAT + n*4];
      sc[SXL + n*68 + t]      = fmaf(la.x, wl0a, fmaf(la.y, wl1a, fmaf(la.z, wl2a, bla)));
      sc[SXL + n*68 + t + 32] = fmaf(la.x, wl0b, fmaf(la.y, wl1b, fmaf(la.z, wl2b, blb)));
      sc[SXR + n*68 + t]      = fmaf(la.x, wr0a, fmaf(la.y, wr1a, fmaf(la.z, wr2a, bra)));
      sc[SXR + n*68 + t + 32] = fmaf(la.x, wr0b, fmaf(la.y, wr1b, fmaf(la.z, wr2b, brb)));
    }
  }
  __syncwarp();

  // ================= GAT1 edge scores + softmax (2 pairs: p=2t, 2t+1) =================
  {
    const int i = t >> 2;
    const int jj = (t & 3) * 2;
    const float* xr = sc + SXR + i*68;
    const float* xa = sc + SXL + jj*68;
    float2 ea = *(const float2*)&sc[SEAT + 2*t];
    float2 mk = *(const float2*)&sc[SMSK + 2*t];
    float acc0 = 0.f, acc1 = 0.f;
#pragma unroll 8
    for (int c = 0; c < 64; c += 4) {
      float4 r  = *(const float4*)&xr[c];
      float4 l0 = *(const float4*)&xa[c];
      float4 l1 = *(const float4*)&xa[c + 68];
      float4 we = *(const float4*)&ws[G1WE + c];
      float4 at = *(const float4*)&ws[G1ATT + c];
      acc0 = fmaf(lrelu(fmaf(ea.x, we.x, r.x) + l0.x), at.x, acc0);
      acc1 = fmaf(lrelu(fmaf(ea.y, we.x, r.x) + l1.x), at.x, acc1);
      acc0 = fmaf(lrelu(fmaf(ea.x, we.y, r.y) + l0.y), at.y, acc0);
      acc1 = fmaf(lrelu(fmaf(ea.y, we.y, r.y) + l1.y), at.y, acc1);
      acc0 = fmaf(lrelu(fmaf(ea.x, we.z, r.z) + l0.z), at.z, acc0);
      acc1 = fmaf(lrelu(fmaf(ea.y, we.z, r.z) + l1.z), at.z, acc1);
      acc0 = fmaf(lrelu(fmaf(ea.x, we.w, r.w) + l0.w), at.w, acc0);
      acc1 = fmaf(lrelu(fmaf(ea.y, we.w, r.w) + l1.w), at.w, acc1);
    }
    float e0 = (mk.x != 0.f) ? acc0 : -1e30f;
    float e1 = (mk.y != 0.f) ? acc1 : -1e30f;
    float m = fmaxf(e0, e1);
    m = fmaxf(m, __shfl_xor_sync(0xffffffffu, m, 1));
    m = fmaxf(m, __shfl_xor_sync(0xffffffffu, m, 2));
    float x0 = __expf(e0 - m), x1 = __expf(e1 - m);
    float sden = x0 + x1;
    sden += __shfl_xor_sync(0xffffffffu, sden, 1);
    sden += __shfl_xor_sync(0xffffffffu, sden, 2);
    float inv = 1.f / sden;
    *(float2*)&sc[SALPHA + 2*t] = make_float2(x0*inv*mk.x, x1*inv*mk.y);
  }
  __syncwarp();

  // ================= GAT1 aggregation -> h1 (into SXR), relu =================
  {
    float acc1[8], acc2[8];
    float b1 = ws[G1BIAS + t], b2 = ws[G1BIAS + t + 32];
#pragma unroll
    for (int i = 0; i < 8; i++) { acc1[i] = b1; acc2[i] = b2; }
#pragma unroll
    for (int j = 0; j < 8; j++) {
      float xv1 = sc[SXL + j*68 + t];
      float xv2 = sc[SXL + j*68 + t + 32];
#pragma unroll
      for (int i = 0; i < 8; i++) {
        float al = sc[SALPHA + i*8 + j];
        acc1[i] = fmaf(al, xv1, acc1[i]);
        acc2[i] = fmaf(al, xv2, acc2[i]);
      }
    }
    __syncwarp();   // all edge-phase reads of SXR done before overwrite
#pragma unroll
    for (int i = 0; i < 8; i++) {
      sc[SXR + i*68 + t]      = fmaxf(acc1[i], 0.f);
      sc[SXR + i*68 + t + 32] = fmaxf(acc2[i], 0.f);
    }
  }
  __syncwarp();

  // ================= GAT2 linear (64->3 xl2, xr2) =================
  if (t < 24) {
    float a1 = ws[G2BL4 + l3], a2 = ws[G2BR4 + l3];
    const float* h1p = sc + SXR + n3*68;
#pragma unroll
    for (int c = 0; c < 64; c += 4) {
      float4 h  = *(const float4*)&h1p[c];
      float4 wl = *(const float4*)&ws[G2WLT + l3*64 + c];
      float4 wr = *(const float4*)&ws[G2WRT + l3*64 + c];
      a1 = fmaf(h.x, wl.x, fmaf(h.y, wl.y, fmaf(h.z, wl.z, fmaf(h.w, wl.w, a1))));
      a2 = fmaf(h.x, wr.x, fmaf(h.y, wr.y, fmaf(h.z, wr.z, fmaf(h.w, wr.w, a2))));
    }
    sc[SXL2 + n3*4 + l3] = a1;
    sc[SXR2 + n3*4 + l3] = a2;
  }
  __syncwarp();

  // ================= GAT2 edge scores + softmax =================
  {
    const int i = t >> 2;
    const int jj = (t & 3) * 2;
    float4 r   = *(const float4*)&sc[SXR2 + i*4];
    float4 l0  = *(const float4*)&sc[SXL2 + jj*4];
    float4 l1  = *(const float4*)&sc[SXL2 + (jj+1)*4];
    float4 we  = *(const float4*)&ws[G2WE4];
    float4 at  = *(const float4*)&ws[G2ATT4];
    float2 ea = *(const float2*)&sc[SEAT + 2*t];
    float2 mk = *(const float2*)&sc[SMSK + 2*t];
    float acc0 = 0.f, acc1 = 0.f;
    acc0 = fmaf(lrelu(fmaf(ea.x, we.x, r.x) + l0.x), at.x, acc0);
    acc1 = fmaf(lrelu(fmaf(ea.y, we.x, r.x) + l1.x), at.x, acc1);
    acc0 = fmaf(lrelu(fmaf(ea.x, we.y, r.y) + l0.y), at.y, acc0);
    acc1 = fmaf(lrelu(fmaf(ea.y, we.y, r.y) + l1.y), at.y, acc1);
    acc0 = fmaf(lrelu(fmaf(ea.x, we.z, r.z) + l0.z), at.z, acc0);
    acc1 = fmaf(lrelu(fmaf(ea.y, we.z, r.z) + l1.z), at.z, acc1);
    float e0 = (mk.x != 0.f) ? acc0 : -1e30f;
    float e1 = (mk.y != 0.f) ? acc1 : -1e30f;
    float m = fmaxf(e0, e1);
    m = fmaxf(m, __shfl_xor_sync(0xffffffffu, m, 1));
    m = fmaxf(m, __shfl_xor_sync(0xffffffffu, m, 2));
    float x0 = __expf(e0 - m), x1 = __expf(e1 - m);
    float sden = x0 + x1;
    sden += __shfl_xor_sync(0xffffffffu, sden, 1);
    sden += __shfl_xor_sync(0xffffffffu, sden, 2);
    float inv = 1.f / sden;
    *(float2*)&sc[SALPHA + 2*t] = make_float2(x0*inv*mk.x, x1*inv*mk.y);
  }
  __syncwarp();

  // ================= GAT2 aggregation + skip -> combined =================
  if (t < 24) {
    float acc = ws[G2BIAS4 + l3];
#pragma unroll
    for (int j = 0; j < 8; j++)
      acc = fmaf(sc[SALPHA + n3*8 + j], sc[SXL2 + j*4 + l3], acc);
    float4 la = *(const float4*)&sc[SLAT + n3*4];
    acc += fmaf(la.x, ws[SKW + l3],
           fmaf(la.y, ws[SKW + 3 + l3],
           fmaf(la.z, ws[SKW + 6 + l3], ws[SKB + l3])));
    sc[SCOMB + n3*4 + l3] = acc;
  }
  __syncwarp();

  // ================= decoder L1 (3->64) =================
  {
    float w0a=ws[DW1+t],    w1a=ws[DW1+64+t],    w2a=ws[DW1+128+t],    ba=ws[DB1+t];
    float w0b=ws[DW1+t+32], w1b=ws[DW1+64+t+32], w2b=ws[DW1+128+t+32], bb=ws[DB1+t+32];
    float va[8], vb[8];
#pragma unroll
    for (int n = 0; n < 8; n++) {
      float4 cm = *(const float4*)&sc[SCOMB + n*4];
      va[n] = fmaxf(fmaf(cm.x, w0a, fmaf(cm.y, w1a, fmaf(cm.z, w2a, ba))), 0.f);
      vb[n] = fmaxf(fmaf(cm.x, w0b, fmaf(cm.y, w1b, fmaf(cm.z, w2b, bb))), 0.f);
    }
    *(float4*)&sc[SA + t*8]          = make_float4(va[0],va[1],va[2],va[3]);
    *(float4*)&sc[SA + t*8 + 4]      = make_float4(va[4],va[5],va[6],va[7]);
    *(float4*)&sc[SA + (t+32)*8]     = make_float4(vb[0],vb[1],vb[2],vb[3]);
    *(float4*)&sc[SA + (t+32)*8 + 4] = make_float4(vb[4],vb[5],vb[6],vb[7]);
  }
  __syncwarp();

  // ================= decoder L2 (64x64) =================
  mlp64(sc + SA, sc + SB, ws + DW2P, ws + DB2P, t);
  __syncwarp();

  // ================= decoder L3 (64->3) -> rec output =================
  if (t < 24) {
    float acc = ws[DB3 + l3];
#pragma unroll 16
    for (int k = 0; k < 64; k++)
      acc = fmaf(sc[SB + k*8 + n3], ws[DW3 + k*3 + l3], acc);
    out[Btot*24 + s*24 + t] = acc;
  }
}

extern "C" void kernel_launch(void* const* d_in, const int* in_sizes, int n_in,
                              void* d_out, int out_size)
{
  (void)n_in; (void)out_size;
  KParams kp;
  kp.x = (const float*)d_in[0];
  for (int i = 0; i < 28; i++) kp.w[i] = (const float*)d_in[i + 1];
  kp.B = in_sizes[0] / 8;

  cudaFuncSetAttribute(gae3_kernel, cudaFuncAttributeMaxDynamicSharedMemorySize, SMEM_BYTES);
  int grid = (kp.B + SPB - 1) / SPB;
  gae3_kernel<<<grid, THREADS, SMEM_BYTES>>>(kp, (float*)d_out);
}

// round 4
// speedup vs baseline: 2.1752x; 1.0096x over previous
#include <cuda_runtime.h>

#define SPB 12           // samples per block (1 warp per sample; warp pairs share MLP weights)
#define THREADS 384

// ---- weight offsets in shared (floats) ----
enum {
  EW1=0, EB1=192, EW2P=256, EB2P=4352, EW3P=4416, EB3=4672,
  G1WL=4676, G1BL=4868, G1WR=4932, G1BR=5124, G1WE=5188, G1ATT=5252, G1BIAS=5316,
  G2WLT=5380, G2BL4=5572, G2WRT=5576, G2BR4=5768,
  G2WE4=5772, G2ATT4=5776, G2BIAS4=5780,
  SKW=5784, SKB=5796,
  DW1=5800, DB1=5992, DW2P=6056, DB2P=10152, DW3P=10216, DB3=10472,
  WTOT=10476
};
// ---- per-sample scratch offsets (floats) ----
// U region: SA=[0,512) | SLATP=[512,560) | SXL=[0,544) SXR=[544,1088)  (disjoint lifetimes)
enum {
  SA=0, SLATP=512, SXL=0, SXR=544,
  SEAT=1088, SMSK=1152, SALPHA=1216,
  SLAT=1280, SVIS=1312, SCOMB=1344, SXL2=1376, SXR2=1408, SX=1440,
  SPER=1456
};

#define SMEM_FLOATS (WTOT + SPB*SPER)
#define SMEM_BYTES  (SMEM_FLOATS*4)   // 111,792 bytes -> 2 blocks/SM

struct KParams {
  const float* x;
  const float* w[28];
  int B;
};

extern __shared__ float smem[];

__device__ __forceinline__ void cpy(float* dst, const float* src, int n, int tid) {
  for (int i = tid; i < n; i += THREADS) dst[i] = src[i];
}

__device__ __forceinline__ float lrelu(float h) {
  return fmaxf(h, 0.f) + 0.2f*fminf(h, 0.f);
}

__device__ __forceinline__ float4 relu4(float4 a) {
  return make_float4(fmaxf(a.x,0.f), fmaxf(a.y,0.f), fmaxf(a.z,0.f), fmaxf(a.w,0.f));
}

// Paired 8x64 @ 64x64 + relu + fused (64->3) projection partials.
// Warp pair: h = warp&1 selects channel half [h*32, h*32+32).
// Thread: cg=t&7 (4 channels), sh=(t>>3)&1 (sample), ng=t>>4 (nodes 4ng..4ng+3).
// Leaves per-(h,sample) partial [node][l] sums (over this warp's 32 channels)
// in scp[SLATP + h*24 + node*3 + l]; trailing pair barrier included.
__device__ __forceinline__ void mlp64_pair_partial(
    const float* __restrict__ inA, const float* __restrict__ inB,
    float* scA, float* scB,
    const float* __restrict__ Wp, const float* __restrict__ bp,
    const float* __restrict__ W3p,
    int t, int h, int barid)
{
  const int cg = t & 7, sh = (t >> 3) & 1, ng = t >> 4;
  const float* in = sh ? inB : inA;
  float* scp = sh ? scB : scA;
  const float* wp = Wp + h*32 + cg*4;
  float4 b4 = *(const float4*)&bp[h*32 + cg*4];
  float4 A0 = make_float4(b4.x, b4.x, b4.x, b4.x);
  float4 A1 = make_float4(b4.y, b4.y, b4.y, b4.y);
  float4 A2 = make_float4(b4.z, b4.z, b4.z, b4.z);
  float4 A3 = make_float4(b4.w, b4.w, b4.w, b4.w);
  const float* ap = in + 4*ng;
#pragma unroll 8
  for (int k = 0; k < 64; k++) {
    float4 av = *(const float4*)&ap[k*8];
    float4 wv = *(const float4*)&wp[k*64];
    A0.x = fmaf(wv.x, av.x, A0.x); A0.y = fmaf(wv.x, av.y, A0.y);
    A0.z = fmaf(wv.x, av.z, A0.z); A0.w = fmaf(wv.x, av.w, A0.w);
    A1.x = fmaf(wv.y, av.x, A1.x); A1.y = fmaf(wv.y, av.y, A1.y);
    A1.z = fmaf(wv.y, av.z, A1.z); A1.w = fmaf(wv.y, av.w, A1.w);
    A2.x = fmaf(wv.z, av.x, A2.x); A2.y = fmaf(wv.z, av.y, A2.y);
    A2.z = fmaf(wv.z, av.z, A2.z); A2.w = fmaf(wv.z, av.w, A2.w);
    A3.x = fmaf(wv.w, av.x, A3.x); A3.y = fmaf(wv.w, av.y, A3.y);
    A3.z = fmaf(wv.w, av.z, A3.z); A3.w = fmaf(wv.w, av.w, A3.w);
  }
  A0 = relu4(A0); A1 = relu4(A1); A2 = relu4(A2); A3 = relu4(A3);

  const int p0i = h*32 + cg*4;
  float4 E0 = *(const float4*)&W3p[(p0i+0)*4];
  float4 E1 = *(const float4*)&W3p[(p0i+1)*4];
  float4 E2 = *(const float4*)&W3p[(p0i+2)*4];
  float4 E3 = *(const float4*)&W3p[(p0i+3)*4];

  // p_l (float4 over nodes) = sum_u A_u * E_u.l
  float4 p0, p1, p2;
  p0.x = fmaf(A0.x,E0.x, fmaf(A1.x,E1.x, fmaf(A2.x,E2.x, A3.x*E3.x)));
  p0.y = fmaf(A0.y,E0.x, fmaf(A1.y,E1.x, fmaf(A2.y,E2.x, A3.y*E3.x)));
  p0.z = fmaf(A0.z,E0.x, fmaf(A1.z,E1.x, fmaf(A2.z,E2.x, A3.z*E3.x)));
  p0.w = fmaf(A0.w,E0.x, fmaf(A1.w,E1.x, fmaf(A2.w,E2.x, A3.w*E3.x)));
  p1.x = fmaf(A0.x,E0.y, fmaf(A1.x,E1.y, fmaf(A2.x,E2.y, A3.x*E3.y)));
  p1.y = fmaf(A0.y,E0.y, fmaf(A1.y,E1.y, fmaf(A2.y,E2.y, A3.y*E3.y)));
  p1.z = fmaf(A0.z,E0.y, fmaf(A1.z,E1.y, fmaf(A2.z,E2.y, A3.z*E3.y)));
  p1.w = fmaf(A0.w,E0.y, fmaf(A1.w,E1.y, fmaf(A2.w,E2.y, A3.w*E3.y)));
  p2.x = fmaf(A0.x,E0.z, fmaf(A1.x,E1.z, fmaf(A2.x,E2.z, A3.x*E3.z)));
  p2.y = fmaf(A0.y,E0.z, fmaf(A1.y,E1.z, fmaf(A2.y,E2.z, A3.y*E3.z)));
  p2.z = fmaf(A0.z,E0.z, fmaf(A1.z,E1.z, fmaf(A2.z,E2.z, A3.z*E3.z)));
  p2.w = fmaf(A0.w,E0.z, fmaf(A1.w,E1.z, fmaf(A2.w,E2.z, A3.w*E3.z)));

#pragma unroll
  for (int m = 1; m <= 4; m <<= 1) {
    p0.x += __shfl_xor_sync(0xffffffffu, p0.x, m);
    p0.y += __shfl_xor_sync(0xffffffffu, p0.y, m);
    p0.z += __shfl_xor_sync(0xffffffffu, p0.z, m);
    p0.w += __shfl_xor_sync(0xffffffffu, p0.w, m);
    p1.x += __shfl_xor_sync(0xffffffffu, p1.x, m);
    p1.y += __shfl_xor_sync(0xffffffffu, p1.y, m);
    p1.z += __shfl_xor_sync(0xffffffffu, p1.z, m);
    p1.w += __shfl_xor_sync(0xffffffffu, p1.w, m);
    p2.x += __shfl_xor_sync(0xffffffffu, p2.x, m);
    p2.y += __shfl_xor_sync(0xffffffffu, p2.y, m);
    p2.z += __shfl_xor_sync(0xffffffffu, p2.z, m);
    p2.w += __shfl_xor_sync(0xffffffffu, p2.w, m);
  }
  if (cg == 0) {
    float* d = scp + SLATP + h*24 + (4*ng)*3;
    d[0]  = p0.x; d[1]  = p1.x; d[2]  = p2.x;
    d[3]  = p0.y; d[4]  = p1.y; d[5]  = p2.y;
    d[6]  = p0.z; d[7]  = p1.z; d[8]  = p2.z;
    d[9]  = p0.w; d[10] = p1.w; d[11] = p2.w;
  }
  asm volatile("bar.sync %0, 64;" :: "r"(barid) : "memory");
}

__global__ __launch_bounds__(THREADS, 2)
void gae4_kernel(KParams kp, float* __restrict__ out)
{
  float* ws = smem;
  const int tid = threadIdx.x;

  // ================= stage weights =================
  cpy(ws+EW1, kp.w[0], 192, tid); cpy(ws+EB1, kp.w[1], 64, tid);
  cpy(ws+EW2P, kp.w[2], 4096, tid);    // identity layout [k][c]
  cpy(ws+EB2P, kp.w[3], 64, tid);
  { const float* w4 = kp.w[4];
    for (int i = tid; i < 256; i += THREADS) {
      int c = i >> 2, l = i & 3;
      ws[EW3P + i] = (l < 3) ? w4[c*3 + l] : 0.f;
    } }
  if (tid < 4) ws[EB3+tid] = (tid < 3) ? kp.w[5][tid] : 0.f;
  cpy(ws+G1WL, kp.w[6], 192, tid);  cpy(ws+G1BL, kp.w[7], 64, tid);
  cpy(ws+G1WR, kp.w[8], 192, tid);  cpy(ws+G1BR, kp.w[9], 64, tid);
  cpy(ws+G1WE, kp.w[10], 64, tid);  cpy(ws+G1ATT, kp.w[11], 64, tid);
  cpy(ws+G1BIAS, kp.w[12], 64, tid);
  { const float* wl = kp.w[13]; const float* wr = kp.w[15];
    for (int i = tid; i < 192; i += THREADS) {
      int k = i / 3, l = i - k*3;
      ws[G2WLT + l*64 + k] = wl[i];
      ws[G2WRT + l*64 + k] = wr[i];
    } }
  if (tid < 4) {
    ws[G2BL4 + tid]   = (tid < 3) ? kp.w[14][tid] : 0.f;
    ws[G2BR4 + tid]   = (tid < 3) ? kp.w[16][tid] : 0.f;
    ws[G2WE4 + tid]   = (tid < 3) ? kp.w[17][tid] : 0.f;
    ws[G2ATT4 + tid]  = (tid < 3) ? kp.w[18][tid] : 0.f;
    ws[G2BIAS4 + tid] = (tid < 3) ? kp.w[19][tid] : 0.f;
  }
  if (tid < 12) ws[SKW+tid] = (tid < 9) ? kp.w[20][tid] : 0.f;
  if (tid < 4)  ws[SKB+tid] = (tid < 3) ? kp.w[21][tid] : 0.f;
  cpy(ws+DW1, kp.w[22], 192, tid); cpy(ws+DB1, kp.w[23], 64, tid);
  cpy(ws+DW2P, kp.w[24], 4096, tid);
  cpy(ws+DB2P, kp.w[25], 64, tid);
  { const float* w26 = kp.w[26];
    for (int i = tid; i < 256; i += THREADS) {
      int c = i >> 2, l = i & 3;
      ws[DW3P + i] = (l < 3) ? w26[c*3 + l] : 0.f;
    } }
  if (tid < 4) ws[DB3+tid] = (tid < 3) ? kp.w[27][tid] : 0.f;

  const int g = tid >> 5;
  const int t = tid & 31;
  const int h = g & 1;
  const int barid = (g >> 1) + 1;
  float* sc  = smem + WTOT + g*SPER;
  float* scA = smem + WTOT + (g & ~1)*SPER;
  float* scB = scA + SPER;
  const int Btot = kp.B;
  const int s = blockIdx.x*SPB + g;
  const bool valid = (s < Btot);
  const int sl = valid ? s : (Btot - 1);

  if (t < 8) sc[SX + t] = kp.x[sl*8 + t];
  __syncthreads();

  const int n3 = t / 3, l3 = t - n3*3;    // (node, dim) map for t<24 phases

  // ================= encoder L1 (3->64), layout [c][n] stride 8 =================
  {
    float wn1 = ws[EW1+64+t],    wx1 = ws[EW1+128+t],    bb1 = ws[EB1+t];
    float wn2 = ws[EW1+64+t+32], wx2 = ws[EW1+128+t+32], bb2 = ws[EB1+t+32];
    float va[8], vb[8];
#pragma unroll
    for (int n = 0; n < 8; n++) {
      float xn = sc[SX + n];
      va[n] = fmaxf(fmaf(xn, wx1, fmaf((float)n, wn1, bb1)), 0.f);
      vb[n] = fmaxf(fmaf(xn, wx2, fmaf((float)n, wn2, bb2)), 0.f);
    }
    *(float4*)&sc[SA + t*8]          = make_float4(va[0],va[1],va[2],va[3]);
    *(float4*)&sc[SA + t*8 + 4]      = make_float4(va[4],va[5],va[6],va[7]);
    *(float4*)&sc[SA + (t+32)*8]     = make_float4(vb[0],vb[1],vb[2],vb[3]);
    *(float4*)&sc[SA + (t+32)*8 + 4] = make_float4(vb[4],vb[5],vb[6],vb[7]);
  }
  asm volatile("bar.sync %0, 64;" :: "r"(barid) : "memory");

  // ================= encoder L2 (64x64, paired) + fused L3 partials =================
  mlp64_pair_partial(scA + SA, scB + SA, scA, scB, ws + EW2P, ws + EB2P, ws + EW3P,
                     t, h, barid);

  // owner warp combines partial halves -> latent [8][3]
  if (t < 24)
    sc[SLAT + n3*4 + l3] = sc[SLATP + t] + sc[SLATP + 24 + t] + ws[EB3 + l3];
  __syncwarp();

  // ================= normalize -> vis  (lane = l*8+n) =================
  {
    int ln_l = t >> 3, ln_n = t & 7;
    float v = sc[SLAT + ln_n*4 + ((ln_l < 3) ? ln_l : 0)];
    float sm = v;
    sm += __shfl_xor_sync(0xffffffffu, sm, 1);
    sm += __shfl_xor_sync(0xffffffffu, sm, 2);
    sm += __shfl_xor_sync(0xffffffffu, sm, 4);
    float c = v - sm*0.125f;
    float vv = c*c;
    vv += __shfl_xor_sync(0xffffffffu, vv, 1);
    vv += __shfl_xor_sync(0xffffffffu, vv, 2);
    vv += __shfl_xor_sync(0xffffffffu, vv, 4);
    float inv = 1.f / (sqrtf(vv * (1.f/7.f)) + 1e-8f);
    float visv = c*inv;
    if (t < 24) {
      sc[SVIS + ln_n*4 + ln_l] = visv;
      if (valid) {
        out[2*Btot*24 + s*24 + ln_n*3 + ln_l] = visv;    // vis
        float xpv = (l3 == 0) ? 0.f : ((l3 == 1) ? (float)n3 : sc[SX + n3]);
        out[s*24 + t] = xpv;                             // xp
      }
    }
  }
  __syncwarp();

  // ================= Gabriel graph (2 pairs per lane: p=t, p=t+32) =================
  {
    float4 Pv[8];
#pragma unroll
    for (int n = 0; n < 8; n++) Pv[n] = *(const float4*)&sc[SVIS + n*4];
    int i0 = t >> 3, j0 = t & 7;
    int i1 = (t + 32) >> 3;
    float4 pi0 = Pv[i0], pj0 = Pv[j0], pi1 = Pv[i1];
    float a0, d0, a1, d1;
    {
      float mx=(pi0.x+pj0.x)*0.5f, my=(pi0.y+pj0.y)*0.5f, mz=(pi0.z+pj0.z)*0.5f;
      float rx=pi0.x-mx, ry=pi0.y-my, rz=pi0.z-mz;
      float r2 = rx*rx+ry*ry+rz*rz;
      bool viol = false;
#pragma unroll
      for (int k = 0; k < 8; k++) {
        float ex=Pv[k].x-mx, ey=Pv[k].y-my, ez=Pv[k].z-mz;
        float d2 = ex*ex+ey*ey+ez*ez;
        viol |= (k != i0) && (k != j0) && (d2 < r2);
      }
      a0 = (!viol && (i0 != j0)) ? 1.f : 0.f;
      float dx=pi0.x-pj0.x, dy=pi0.y-pj0.y, dz=pi0.z-pj0.z;
      d0 = sqrtf(dx*dx+dy*dy+dz*dz + 1e-30f);
    }
    {
      float mx=(pi1.x+pj0.x)*0.5f, my=(pi1.y+pj0.y)*0.5f, mz=(pi1.z+pj0.z)*0.5f;
      float rx=pi1.x-mx, ry=pi1.y-my, rz=pi1.z-mz;
      float r2 = rx*rx+ry*ry+rz*rz;
      bool viol = false;
#pragma unroll
      for (int k = 0; k < 8; k++) {
        float ex=Pv[k].x-mx, ey=Pv[k].y-my, ez=Pv[k].z-mz;
        float d2 = ex*ex+ey*ey+ez*ez;
        viol |= (k != i1) && (k != j0) && (d2 < r2);
      }
      a1 = (!viol && (i1 != j0)) ? 1.f : 0.f;
      float dx=pi1.x-pj0.x, dy=pi1.y-pj0.y, dz=pi1.z-pj0.z;
      d1 = sqrtf(dx*dx+dy*dy+dz*dz + 1e-30f);
    }
    float as = a0 + a1, ds = a0*d0 + a1*d1;
#pragma unroll
    for (int m = 16; m; m >>= 1) {
      as += __shfl_xor_sync(0xffffffffu, as, m);
      ds += __shfl_xor_sync(0xffffffffu, ds, m);
    }
    float ma = ds / fmaxf(as, 1.f);
    sc[SEAT + t]      = (i0 == j0) ? ma  : d0;
    sc[SEAT + t + 32] = (i1 == j0) ? ma  : d1;
    sc[SMSK + t]      = (i0 == j0) ? 1.f : a0;
    sc[SMSK + t + 32] = (i1 == j0) ? 1.f : a1;
    if (valid) {
      out[3*Btot*24 + s*64 + t]      = a0;               // adj
      out[3*Btot*24 + s*64 + t + 32] = a1;
    }
  }

  // ================= GAT1 linear (3->64 xl, xr)  [n][c] stride 68 =================
  {
    float wl0a=ws[G1WL+t],    wl1a=ws[G1WL+64+t],    wl2a=ws[G1WL+128+t],    bla=ws[G1BL+t];
    float wl0b=ws[G1WL+t+32], wl1b=ws[G1WL+64+t+32], wl2b=ws[G1WL+128+t+32], blb=ws[G1BL+t+32];
    float wr0a=ws[G1WR+t],    wr1a=ws[G1WR+64+t],    wr2a=ws[G1WR+128+t],    bra=ws[G1BR+t];
    float wr0b=ws[G1WR+t+32], wr1b=ws[G1WR+64+t+32], wr2b=ws[G1WR+128+t+32], brb=ws[G1BR+t+32];
#pragma unroll
    for (int n = 0; n < 8; n++) {
      float4 la = *(const float4*)&sc[SLAT + n*4];
      sc[SXL + n*68 + t]      = fmaf(la.x, wl0a, fmaf(la.y, wl1a, fmaf(la.z, wl2a, bla)));
      sc[SXL + n*68 + t + 32] = fmaf(la.x, wl0b, fmaf(la.y, wl1b, fmaf(la.z, wl2b, blb)));
      sc[SXR + n*68 + t]      = fmaf(la.x, wr0a, fmaf(la.y, wr1a, fmaf(la.z, wr2a, bra)));
      sc[SXR + n*68 + t + 32] = fmaf(la.x, wr0b, fmaf(la.y, wr1b, fmaf(la.z, wr2b, brb)));
    }
  }
  __syncwarp();

  // ================= GAT1 edge scores + softmax (2 pairs: p=2t, 2t+1) =================
  {
    const int i = t >> 2;
    const int jj = (t & 3) * 2;
    const float* xr = sc + SXR + i*68;
    const float* xa = sc + SXL + jj*68;
    float2 ea = *(const float2*)&sc[SEAT + 2*t];
    float2 mk = *(const float2*)&sc[SMSK + 2*t];
    float acc0 = 0.f, acc1 = 0.f;
#pragma unroll 8
    for (int c = 0; c < 64; c += 4) {
      float4 r  = *(const float4*)&xr[c];
      float4 l0 = *(const float4*)&xa[c];
      float4 l1 = *(const float4*)&xa[c + 68];
      float4 we = *(const float4*)&ws[G1WE + c];
      float4 at = *(const float4*)&ws[G1ATT + c];
      acc0 = fmaf(lrelu(fmaf(ea.x, we.x, r.x) + l0.x), at.x, acc0);
      acc1 = fmaf(lrelu(fmaf(ea.y, we.x, r.x) + l1.x), at.x, acc1);
      acc0 = fmaf(lrelu(fmaf(ea.x, we.y, r.y) + l0.y), at.y, acc0);
      acc1 = fmaf(lrelu(fmaf(ea.y, we.y, r.y) + l1.y), at.y, acc1);
      acc0 = fmaf(lrelu(fmaf(ea.x, we.z, r.z) + l0.z), at.z, acc0);
      acc1 = fmaf(lrelu(fmaf(ea.y, we.z, r.z) + l1.z), at.z, acc1);
      acc0 = fmaf(lrelu(fmaf(ea.x, we.w, r.w) + l0.w), at.w, acc0);
      acc1 = fmaf(lrelu(fmaf(ea.y, we.w, r.w) + l1.w), at.w, acc1);
    }
    float e0 = (mk.x != 0.f) ? acc0 : -1e30f;
    float e1 = (mk.y != 0.f) ? acc1 : -1e30f;
    float m = fmaxf(e0, e1);
    m = fmaxf(m, __shfl_xor_sync(0xffffffffu, m, 1));
    m = fmaxf(m, __shfl_xor_sync(0xffffffffu, m, 2));
    float x0 = __expf(e0 - m), x1 = __expf(e1 - m);
    float sden = x0 + x1;
    sden += __shfl_xor_sync(0xffffffffu, sden, 1);
    sden += __shfl_xor_sync(0xffffffffu, sden, 2);
    float inv = 1.f / sden;
    *(float2*)&sc[SALPHA + 2*t] = make_float2(x0*inv*mk.x, x1*inv*mk.y);
  }
  __syncwarp();

  // ================= GAT1 aggregation -> h1 (into SXR), relu =================
  {
    float acc1[8], acc2[8];
    float b1 = ws[G1BIAS + t], b2 = ws[G1BIAS + t + 32];
#pragma unroll
    for (int i = 0; i < 8; i++) { acc1[i] = b1; acc2[i] = b2; }
#pragma unroll
    for (int j = 0; j < 8; j += 2) {
      float xv1a = sc[SXL + j*68 + t],       xv2a = sc[SXL + j*68 + t + 32];
      float xv1b = sc[SXL + (j+1)*68 + t],   xv2b = sc[SXL + (j+1)*68 + t + 32];
#pragma unroll
      for (int i = 0; i < 8; i++) {
        float2 al = *(const float2*)&sc[SALPHA + i*8 + j];
        acc1[i] = fmaf(al.x, xv1a, fmaf(al.y, xv1b, acc1[i]));
        acc2[i] = fmaf(al.x, xv2a, fmaf(al.y, xv2b, acc2[i]));
      }
    }
    __syncwarp();
#pragma unroll
    for (int i = 0; i < 8; i++) {
      sc[SXR + i*68 + t]      = fmaxf(acc1[i], 0.f);
      sc[SXR + i*68 + t + 32] = fmaxf(acc2[i], 0.f);
    }
  }
  __syncwarp();

  // ================= GAT2 linear (64->3 xl2, xr2) =================
  if (t < 24) {
    float a1 = ws[G2BL4 + l3], a2 = ws[G2BR4 + l3];
    const float* h1p = sc + SXR + n3*68;
#pragma unroll
    for (int c = 0; c < 64; c += 4) {
      float4 hh = *(const float4*)&h1p[c];
      float4 wl = *(const float4*)&ws[G2WLT + l3*64 + c];
      float4 wr = *(const float4*)&ws[G2WRT + l3*64 + c];
      a1 = fmaf(hh.x, wl.x, fmaf(hh.y, wl.y, fmaf(hh.z, wl.z, fmaf(hh.w, wl.w, a1))));
      a2 = fmaf(hh.x, wr.x, fmaf(hh.y, wr.y, fmaf(hh.z, wr.z, fmaf(hh.w, wr.w, a2))));
    }
    sc[SXL2 + n3*4 + l3] = a1;
    sc[SXR2 + n3*4 + l3] = a2;
  }
  __syncwarp();

  // ================= GAT2 edge scores + softmax =================
  {
    const int i = t >> 2;
    const int jj = (t & 3) * 2;
    float4 r   = *(const float4*)&sc[SXR2 + i*4];
    float4 l0  = *(const float4*)&sc[SXL2 + jj*4];
    float4 l1  = *(const float4*)&sc[SXL2 + (jj+1)*4];
    float4 we  = *(const float4*)&ws[G2WE4];
    float4 at  = *(const float4*)&ws[G2ATT4];
    float2 ea = *(const float2*)&sc[SEAT + 2*t];
    float2 mk = *(const float2*)&sc[SMSK + 2*t];
    float acc0 = 0.f, acc1 = 0.f;
    acc0 = fmaf(lrelu(fmaf(ea.x, we.x, r.x) + l0.x), at.x, acc0);
    acc1 = fmaf(lrelu(fmaf(ea.y, we.x, r.x) + l1.x), at.x, acc1);
    acc0 = fmaf(lrelu(fmaf(ea.x, we.y, r.y) + l0.y), at.y, acc0);
    acc1 = fmaf(lrelu(fmaf(ea.y, we.y, r.y) + l1.y), at.y, acc1);
    acc0 = fmaf(lrelu(fmaf(ea.x, we.z, r.z) + l0.z), at.z, acc0);
    acc1 = fmaf(lrelu(fmaf(ea.y, we.z, r.z) + l1.z), at.z, acc1);
    float e0 = (mk.x != 0.f) ? acc0 : -1e30f;
    float e1 = (mk.y != 0.f) ? acc1 : -1e30f;
    float m = fmaxf(e0, e1);
    m = fmaxf(m, __shfl_xor_sync(0xffffffffu, m, 1));
    m = fmaxf(m, __shfl_xor_sync(0xffffffffu, m, 2));
    float x0 = __expf(e0 - m), x1 = __expf(e1 - m);
    float sden = x0 + x1;
    sden += __shfl_xor_sync(0xffffffffu, sden, 1);
    sden += __shfl_xor_sync(0xffffffffu, sden, 2);
    float inv = 1.f / sden;
    *(float2*)&sc[SALPHA + 2*t] = make_float2(x0*inv*mk.x, x1*inv*mk.y);
  }
  __syncwarp();

  // ================= GAT2 aggregation + skip -> combined =================
  if (t < 24) {
    float acc = ws[G2BIAS4 + l3];
#pragma unroll
    for (int j = 0; j < 8; j++)
      acc = fmaf(sc[SALPHA + n3*8 + j], sc[SXL2 + j*4 + l3], acc);
    float4 la = *(const float4*)&sc[SLAT + n3*4];
    acc += fmaf(la.x, ws[SKW + l3],
           fmaf(la.y, ws[SKW + 3 + l3],
           fmaf(la.z, ws[SKW + 6 + l3], ws[SKB + l3])));
    sc[SCOMB + n3*4 + l3] = acc;
  }
  __syncwarp();

  // ================= decoder L1 (3->64) =================
  {
    float w0a=ws[DW1+t],    w1a=ws[DW1+64+t],    w2a=ws[DW1+128+t],    ba=ws[DB1+t];
    float w0b=ws[DW1+t+32], w1b=ws[DW1+64+t+32], w2b=ws[DW1+128+t+32], bb=ws[DB1+t+32];
    float va[8], vb[8];
#pragma unroll
    for (int n = 0; n < 8; n++) {
      float4 cm = *(const float4*)&sc[SCOMB + n*4];
      va[n] = fmaxf(fmaf(cm.x, w0a, fmaf(cm.y, w1a, fmaf(cm.z, w2a, ba))), 0.f);
      vb[n] = fmaxf(fmaf(cm.x, w0b, fmaf(cm.y, w1b, fmaf(cm.z, w2b, bb))), 0.f);
    }
    *(float4*)&sc[SA + t*8]          = make_float4(va[0],va[1],va[2],va[3]);
    *(float4*)&sc[SA + t*8 + 4]      = make_float4(va[4],va[5],va[6],va[7]);
    *(float4*)&sc[SA + (t+32)*8]     = make_float4(vb[0],vb[1],vb[2],vb[3]);
    *(float4*)&sc[SA + (t+32)*8 + 4] = make_float4(vb[4],vb[5],vb[6],vb[7]);
  }
  asm volatile("bar.sync %0, 64;" :: "r"(barid) : "memory");

  // ================= decoder L2 (64x64, paired) + fused DW3 partials =================
  mlp64_pair_partial(scA + SA, scB + SA, scA, scB, ws + DW2P, ws + DB2P, ws + DW3P,
                     t, h, barid);

  // owner warp combines -> rec output
  if (valid && t < 24)
    out[Btot*24 + s*24 + t] = sc[SLATP + t] + sc[SLATP + 24 + t] + ws[DB3 + l3];
}

extern "C" void kernel_launch(void* const* d_in, const int* in_sizes, int n_in,
                              void* d_out, int out_size)
{
  (void)n_in; (void)out_size;
  KParams kp;
  kp.x = (const float*)d_in[0];
  for (int i = 0; i < 28; i++) kp.w[i] = (const float*)d_in[i + 1];
  kp.B = in_sizes[0] / 8;

  cudaFuncSetAttribute(gae4_kernel, cudaFuncAttributeMaxDynamicSharedMemorySize, SMEM_BYTES);
  int grid = (kp.B + SPB - 1) / SPB;
  gae4_kernel<<<grid, THREADS, SMEM_BYTES>>>(kp, (float*)d_out);
}